// round 9
// baseline (speedup 1.0000x reference)
#include <cuda_runtime.h>
#include <cuda_bf16.h>
#include <math.h>
#include <stdint.h>

// ---------------- Model constants ----------------
#define DEPTH   24
#define DM      192       // d_model
#define DI      384       // d_inner
#define DSTATE  16
#define DTRANK  12
#define DCONV   4
#define LSEQ    401       // NP+1
#define NB      4         // batch
#define MTOK    (NB*LSEQ) // 1604
#define DXP     (DTRANK + 2*DSTATE) // 44
#define CT      24        // scan chunk length

// ---------------- Scratch (device globals; no allocation) ----------------
__device__ float g_hidden  [MTOK*DM];
__device__ float g_residual[MTOK*DM];
__device__ float g_hnorm   [MTOK*DM];
__device__ float g_xz      [MTOK*2*DI];       // [:,0:384]=xx, [:,384:768]=z
__device__ float g_xconv   [2*MTOK*DI];       // per dir, silu(conv(x))
__device__ float g_dbl     [2*MTOK*DXP];      // xproj out [dt_r(12), B(16), C(16)]
__device__ float g_dt      [2*MTOK*DI];       // softplus(dt)
__device__ float g_y       [2*MTOK*DI];       // gated outputs per dir

// ---------------- tf32 helpers ----------------
__device__ __forceinline__ uint32_t f2tf32(float x) {
    uint32_t r;
    asm("cvt.rna.tf32.f32 %0, %1;" : "=r"(r) : "f"(x));
    return r;
}
__device__ __forceinline__ void mma_tf32(float* c, uint32_t a0, uint32_t a1,
                                         uint32_t a2, uint32_t a3,
                                         uint32_t b0, uint32_t b1) {
    asm volatile(
        "mma.sync.aligned.m16n8k8.row.col.f32.tf32.tf32.f32 "
        "{%0,%1,%2,%3}, {%4,%5,%6,%7}, {%8,%9}, {%0,%1,%2,%3};"
        : "+f"(c[0]), "+f"(c[1]), "+f"(c[2]), "+f"(c[3])
        : "r"(a0), "r"(a1), "r"(a2), "r"(a3), "r"(b0), "r"(b1));
}

// ---------------- Patch embed + cls + pos ----------------
__global__ void k_patch(const float* __restrict__ x, const float* __restrict__ pe_w,
                        const float* __restrict__ pe_b, const float* __restrict__ cls,
                        const float* __restrict__ pos)
{
    int p = blockIdx.x;          // 0..399
    int b = blockIdx.y;          // 0..3
    int tid = threadIdx.x;       // 256
    __shared__ float sp[256];
    int ph = p / 200, pw = p % 200;
    int i = tid >> 4, j = tid & 15;
    sp[tid] = x[b*32*3200 + (ph*16 + i)*3200 + pw*16 + j];
    __syncthreads();
    if (tid < DM) {
        int c = tid;
        const float* w = pe_w + c*256;
        float acc = pe_b[c];
        #pragma unroll 8
        for (int k = 0; k < 256; k++) acc += sp[k]*w[k];
        int t = p + 1;
        float v = acc + pos[t*DM + c];
        int m = b*LSEQ + t;
        g_hidden[m*DM + c] = v;
        g_residual[m*DM + c] = v;
        if (p == 0) {
            float cv = cls[c] + pos[c];
            int m0 = b*LSEQ;
            g_hidden[m0*DM + c] = cv;
            g_residual[m0*DM + c] = cv;
        }
    }
}

// ---------------- residual += hidden ; hnorm = rmsnorm(residual)*w ----------------
__global__ void k_prenorm(const float* __restrict__ norm_w)
{
    int warp = threadIdx.x >> 5, lane = threadIdx.x & 31;
    int m = blockIdx.x*8 + warp;
    if (m >= MTOK) return;
    float r[6]; float ss = 0.f;
    #pragma unroll
    for (int u = 0; u < 6; u++) {
        int c = lane + u*32;
        float v = g_residual[m*DM + c] + g_hidden[m*DM + c];
        r[u] = v; ss += v*v;
        g_residual[m*DM + c] = v;
    }
    #pragma unroll
    for (int o = 16; o; o >>= 1) ss += __shfl_xor_sync(~0u, ss, o);
    float rstd = rsqrtf(ss*(1.f/DM) + 1e-5f);
    #pragma unroll
    for (int u = 0; u < 6; u++) {
        int c = lane + u*32;
        g_hnorm[m*DM + c] = r[u]*rstd*norm_w[c];
    }
}

// ---------------- Tensor-core tf32 GEMM (3xTF32: Al*Wh + Ah*Wl + Ah*Wh) ----------------
// MODE 0: C=g_xz[1604,768] = g_hnorm[1604,192] @ W[768,192]^T     BM=128
// MODE 1: C=g_hidden[1604,192] = (y0+y1)[1604,384] @ W[192,384]^T BM=64
template<int MODE>
__global__ void k_gemm_tc(const float* __restrict__ W)
{
    constexpr int BM = (MODE == 0) ? 128 : 64;
    constexpr int KK = (MODE == 0) ? DM : DI;
    constexpr int NK = KK/16;
    constexpr int MA = (MODE == 0) ? 2 : 1;      // m16 atoms per warp
    constexpr int LDC = (MODE == 0) ? 2*DI : DM;

    __shared__ uint2 Ah[2][2][BM][4];
    __shared__ uint2 Al[2][2][BM][4];
    __shared__ uint2 Bh[2][2][64][4];
    __shared__ uint2 Bl[2][2][64][4];

    int tid = threadIdx.x;                 // 256
    int warp = tid >> 5, lane = tid & 31;
    int g = lane >> 2, tg = lane & 3;
    int m0 = blockIdx.x*BM, n0 = blockIdx.y*64;
    int mw = warp >> 1, nw = warp & 1;
    int mbase = mw*(BM/4), nbase = nw*32;

    // loader roles
    bool doA = (tid < 2*BM);
    int ar = tid >> 1, aks = tid & 1;
    int wt = (MODE == 0) ? tid : (tid - 128);
    bool doW = (MODE == 0) ? (tid < 128) : (tid >= 128);
    int wn = wt >> 1, wks = wt & 1;

    float af[8];   // raw A row slice (8 floats)
    float wf[8];   // raw W row slice

    auto ldA = [&](int k0) {
        if (!doA) return;
        int m = m0 + ar;
        if (m < MTOK) {
            if (MODE == 0) {
                float4 v0 = *(const float4*)(g_hnorm + (size_t)m*KK + k0 + aks*8);
                float4 v1 = *(const float4*)(g_hnorm + (size_t)m*KK + k0 + aks*8 + 4);
                af[0]=v0.x; af[1]=v0.y; af[2]=v0.z; af[3]=v0.w;
                af[4]=v1.x; af[5]=v1.y; af[6]=v1.z; af[7]=v1.w;
            } else {
                float4 a0 = *(const float4*)(g_y + (size_t)m*DI + k0 + aks*8);
                float4 b0 = *(const float4*)(g_y + (size_t)MTOK*DI + (size_t)m*DI + k0 + aks*8);
                float4 a1 = *(const float4*)(g_y + (size_t)m*DI + k0 + aks*8 + 4);
                float4 b1 = *(const float4*)(g_y + (size_t)MTOK*DI + (size_t)m*DI + k0 + aks*8 + 4);
                af[0]=a0.x+b0.x; af[1]=a0.y+b0.y; af[2]=a0.z+b0.z; af[3]=a0.w+b0.w;
                af[4]=a1.x+b1.x; af[5]=a1.y+b1.y; af[6]=a1.z+b1.z; af[7]=a1.w+b1.w;
            }
        } else {
            #pragma unroll
            for (int j = 0; j < 8; j++) af[j] = 0.f;
        }
    };
    auto ldW = [&](int k0) {
        if (!doW) return;
        float4 v0 = *(const float4*)(W + (size_t)(n0 + wn)*KK + k0 + wks*8);
        float4 v1 = *(const float4*)(W + (size_t)(n0 + wn)*KK + k0 + wks*8 + 4);
        wf[0]=v0.x; wf[1]=v0.y; wf[2]=v0.z; wf[3]=v0.w;
        wf[4]=v1.x; wf[5]=v1.y; wf[6]=v1.z; wf[7]=v1.w;
    };
    auto stA = [&](int buf) {
        if (!doA) return;
        #pragma unroll
        for (int j = 0; j < 4; j++) {
            uint32_t h0 = f2tf32(af[j]);
            uint32_t h1 = f2tf32(af[j+4]);
            float l0 = af[j]   - __uint_as_float(h0);
            float l1 = af[j+4] - __uint_as_float(h1);
            Ah[buf][aks][ar][j] = make_uint2(h0, h1);
            Al[buf][aks][ar][j] = make_uint2(f2tf32(l0), f2tf32(l1));
        }
    };
    auto stW = [&](int buf) {
        if (!doW) return;
        #pragma unroll
        for (int j = 0; j < 4; j++) {
            uint32_t h0 = f2tf32(wf[j]);
            uint32_t h1 = f2tf32(wf[j+4]);
            float l0 = wf[j]   - __uint_as_float(h0);
            float l1 = wf[j+4] - __uint_as_float(h1);
            Bh[buf][wks][wn][j] = make_uint2(h0, h1);
            Bl[buf][wks][wn][j] = make_uint2(f2tf32(l0), f2tf32(l1));
        }
    };

    float acc[MA][4][4] = {};

    ldA(0); ldW(0); stA(0); stW(0);
    __syncthreads();

    for (int kt = 0; kt < NK; kt++) {
        if (kt + 1 < NK) { ldA((kt+1)*16); ldW((kt+1)*16); }
        int buf = kt & 1;
        #pragma unroll
        for (int s = 0; s < 2; s++) {
            uint2 bh[4], bl[4];
            #pragma unroll
            for (int na = 0; na < 4; na++) {
                bh[na] = Bh[buf][s][nbase + na*8 + g][tg];
                bl[na] = Bl[buf][s][nbase + na*8 + g][tg];
            }
            #pragma unroll
            for (int ma = 0; ma < MA; ma++) {
                int r0 = mbase + ma*16 + g;
                uint2 h02 = Ah[buf][s][r0][tg];
                uint2 h13 = Ah[buf][s][r0 + 8][tg];
                uint2 l02 = Al[buf][s][r0][tg];
                uint2 l13 = Al[buf][s][r0 + 8][tg];
                #pragma unroll
                for (int na = 0; na < 4; na++) {
                    mma_tf32(acc[ma][na], l02.x, l13.x, l02.y, l13.y, bh[na].x, bh[na].y);
                    mma_tf32(acc[ma][na], h02.x, h13.x, h02.y, h13.y, bl[na].x, bl[na].y);
                    mma_tf32(acc[ma][na], h02.x, h13.x, h02.y, h13.y, bh[na].x, bh[na].y);
                }
            }
        }
        if (kt + 1 < NK) { stA(buf ^ 1); stW(buf ^ 1); }
        __syncthreads();
    }

    float* C = (MODE == 0) ? g_xz : g_hidden;
    #pragma unroll
    for (int ma = 0; ma < MA; ma++) {
        int row0 = m0 + mbase + ma*16 + g;
        int row1 = row0 + 8;
        #pragma unroll
        for (int na = 0; na < 4; na++) {
            int col = n0 + nbase + na*8 + tg*2;
            if (row0 < MTOK)
                *(float2*)(C + (size_t)row0*LDC + col) = make_float2(acc[ma][na][0], acc[ma][na][1]);
            if (row1 < MTOK)
                *(float2*)(C + (size_t)row1*LDC + col) = make_float2(acc[ma][na][2], acc[ma][na][3]);
        }
    }
}

// ---------------- causal dwconv + silu, both dirs ----------------
__global__ void k_conv(const float* __restrict__ cw, const float* __restrict__ cb)
{
    int t = blockIdx.x, b = blockIdx.y;
    int d = threadIdx.x;              // 384
    float w0 = cw[d*4+0], w1 = cw[d*4+1], w2 = cw[d*4+2], w3 = cw[d*4+3];
    float bias = cb[d];
    int rowbase = b*LSEQ;
    float accf = bias;
    if (t-3 >= 0) accf = fmaf(g_xz[(rowbase + t-3)*2*DI + d], w0, accf);
    if (t-2 >= 0) accf = fmaf(g_xz[(rowbase + t-2)*2*DI + d], w1, accf);
    if (t-1 >= 0) accf = fmaf(g_xz[(rowbase + t-1)*2*DI + d], w2, accf);
    accf = fmaf(g_xz[(rowbase + t)*2*DI + d], w3, accf);
    g_xconv[(rowbase + t)*DI + d] = accf / (1.f + __expf(-accf));
    float accb = bias;
    if (t+3 <= LSEQ-1) accb = fmaf(g_xz[(rowbase + t+3)*2*DI + d], w0, accb);
    if (t+2 <= LSEQ-1) accb = fmaf(g_xz[(rowbase + t+2)*2*DI + d], w1, accb);
    if (t+1 <= LSEQ-1) accb = fmaf(g_xz[(rowbase + t+1)*2*DI + d], w2, accb);
    accb = fmaf(g_xz[(rowbase + t)*2*DI + d], w3, accb);
    g_xconv[(MTOK + rowbase + t)*DI + d] = accb / (1.f + __expf(-accb));
}

// ---------------- GEMM2: g_dbl[3208,44] = g_xconv[3208,384] @ W[44,384]^T ----------------
__global__ void k_gemm2(const float* __restrict__ W)
{
    __shared__ float As[32][34];   // [k][m]
    __shared__ float Ws[32][52];   // [k][n]
    int tid = threadIdx.x;         // 192
    int m0 = blockIdx.x*32;
    int ty = tid / 12, tx = tid % 12;
    float acc[2][4] = {};
    for (int k0 = 0; k0 < DI; k0 += 32) {
        for (int i = tid; i < 256; i += 192) {
            int mr = i >> 3, kq = i & 7;
            int m = m0 + mr;
            float4 v = make_float4(0,0,0,0);
            if (m < 2*MTOK) v = *(const float4*)(g_xconv + (size_t)m*DI + k0 + kq*4);
            As[kq*4+0][mr]=v.x; As[kq*4+1][mr]=v.y; As[kq*4+2][mr]=v.z; As[kq*4+3][mr]=v.w;
        }
        for (int i = tid; i < 384; i += 192) {
            int nr = i >> 3, kq = i & 7;
            float4 v = make_float4(0,0,0,0);
            if (nr < DXP) v = *(const float4*)(W + nr*DI + k0 + kq*4);
            Ws[kq*4+0][nr]=v.x; Ws[kq*4+1][nr]=v.y; Ws[kq*4+2][nr]=v.z; Ws[kq*4+3][nr]=v.w;
        }
        __syncthreads();
        #pragma unroll
        for (int k = 0; k < 32; k++) {
            float2 a = *(const float2*)&As[k][ty*2];
            float4 w4 = *(const float4*)&Ws[k][tx*4];
            acc[0][0]=fmaf(a.x,w4.x,acc[0][0]); acc[0][1]=fmaf(a.x,w4.y,acc[0][1]);
            acc[0][2]=fmaf(a.x,w4.z,acc[0][2]); acc[0][3]=fmaf(a.x,w4.w,acc[0][3]);
            acc[1][0]=fmaf(a.y,w4.x,acc[1][0]); acc[1][1]=fmaf(a.y,w4.y,acc[1][1]);
            acc[1][2]=fmaf(a.y,w4.z,acc[1][2]); acc[1][3]=fmaf(a.y,w4.w,acc[1][3]);
        }
        __syncthreads();
    }
    if (tx < 11) {
        #pragma unroll
        for (int i2 = 0; i2 < 2; i2++) {
            int m = m0 + ty*2 + i2;
            if (m < 2*MTOK) {
                float4 v = make_float4(acc[i2][0], acc[i2][1], acc[i2][2], acc[i2][3]);
                *(float4*)(g_dbl + (size_t)m*DXP + tx*4) = v;
            }
        }
    }
}

// ---------------- dt projection ----------------
__global__ void k_dt(const float* __restrict__ dtw, const float* __restrict__ dtb)
{
    int m0 = blockIdx.x*8;
    int ch = threadIdx.x;          // 384
    __shared__ float sdb[8][12];
    if (ch < 96) {
        int r = ch / 12, j = ch % 12;
        sdb[r][j] = g_dbl[(size_t)(m0 + r)*DXP + j];
    }
    float wr[12];
    #pragma unroll
    for (int r = 0; r < 12; r++) wr[r] = dtw[ch*DTRANK + r];
    float bias = dtb[ch];
    __syncthreads();
    #pragma unroll
    for (int q = 0; q < 8; q++) {
        float s = bias;
        #pragma unroll
        for (int r = 0; r < 12; r++) s = fmaf(sdb[q][r], wr[r], s);
        float sp = (s > 20.f) ? s : log1pf(__expf(s));
        g_dt[(size_t)(m0 + q)*DI + ch] = sp;
    }
}

// ---------------- selective scan ----------------
__global__ void k_scan(const float* __restrict__ Alog_f, const float* __restrict__ Alog_b,
                       const float* __restrict__ Dp)
{
    int cblk = blockIdx.x;  // 0..23
    int b = blockIdx.y;
    int dir = blockIdx.z;
    int tid = threadIdx.x;  // 256
    int warp = tid >> 5, lane = tid & 31;
    int dloc = warp*2 + (lane >> 4);
    int n = lane & 15;
    int d = cblk*16 + dloc;

    __shared__ float sbuf[2][5][CT*16];   // 0=dt 1=xv 2=B 3=C 4=z
    __shared__ float sp[CT][16][20];
    __shared__ float s_Dk[16];
    if (tid < 16) s_Dk[tid] = Dp[cblk*16 + tid];

    const float* Alog = dir ? Alog_b : Alog_f;
    float A = -__expf(Alog[d*DSTATE + n]);
    int rowbase = b*LSEQ;
    int gbase = dir*MTOK + rowbase;

    auto stage = [&](int t0, int bf) {
        if (tid < 96) {
            int tt = t0 + (tid >> 2);
            if (tt < LSEQ) {
                int mm = dir ? (LSEQ-1 - tt) : tt;
                int gi = gbase + mm;
                int jq = (tid & 3)*4;
                int idx = (tt - t0)*16 + jq;
                *(float4*)&sbuf[bf][0][idx] = *(const float4*)(g_dt    + (size_t)gi*DI + cblk*16 + jq);
                *(float4*)&sbuf[bf][1][idx] = *(const float4*)(g_xconv + (size_t)gi*DI + cblk*16 + jq);
                *(float4*)&sbuf[bf][2][idx] = *(const float4*)(g_dbl   + (size_t)gi*DXP + DTRANK + jq);
                *(float4*)&sbuf[bf][3][idx] = *(const float4*)(g_dbl   + (size_t)gi*DXP + DTRANK + DSTATE + jq);
                *(float4*)&sbuf[bf][4][idx] = *(const float4*)(g_xz    + (size_t)(rowbase+mm)*2*DI + DI + cblk*16 + jq);
            }
        }
    };

    stage(0, 0);
    __syncthreads();

    float h = 0.f;
    const int nch = (LSEQ + CT - 1)/CT;   // 17
    for (int c = 0; c < nch; c++) {
        int bf = c & 1;
        int tmax = min(CT, LSEQ - c*CT);
        #pragma unroll 4
        for (int k = 0; k < tmax; k++) {
            float dt = sbuf[bf][0][k*16 + dloc];
            float xv = sbuf[bf][1][k*16 + dloc];
            float Bn = sbuf[bf][2][k*16 + n];
            float Cn = sbuf[bf][3][k*16 + n];
            h = fmaf(__expf(dt*A), h, dt*xv*Bn);
            sp[k][dloc][n] = h*Cn;
        }
        __syncthreads();
        if (c + 1 < nch) stage((c+1)*CT, bf ^ 1);
        for (int o = tid; o < tmax*16; o += 256) {
            int k = o >> 4, dd = o & 15;
            float4 p0 = *(const float4*)&sp[k][dd][0];
            float4 p1 = *(const float4*)&sp[k][dd][4];
            float4 p2 = *(const float4*)&sp[k][dd][8];
            float4 p3 = *(const float4*)&sp[k][dd][12];
            float s = ((p0.x+p0.y)+(p0.z+p0.w)) + ((p1.x+p1.y)+(p1.z+p1.w))
                    + ((p2.x+p2.y)+(p2.z+p2.w)) + ((p3.x+p3.y)+(p3.z+p3.w));
            float xvv = sbuf[bf][1][k*16 + dd];
            float z   = sbuf[bf][4][k*16 + dd];
            float y = fmaf(xvv, s_Dk[dd], s);
            int tglob = c*CT + k;
            int mm = dir ? (LSEQ-1 - tglob) : tglob;
            g_y[(size_t)(gbase + mm)*DI + cblk*16 + dd] = y * (z / (1.f + __expf(-z)));
        }
        __syncthreads();
    }
}

// ---------------- final norm + head (cls token only) ----------------
__global__ void k_head(const float* __restrict__ nfw, const float* __restrict__ hw,
                       const float* __restrict__ hb, float* __restrict__ out)
{
    int b = blockIdx.x;
    int tid = threadIdx.x; // 192
    __shared__ float rn[DM];
    __shared__ float red[6];
    int m = b*LSEQ;
    float v = g_residual[m*DM + tid] + g_hidden[m*DM + tid];
    float ss = v*v;
    #pragma unroll
    for (int o = 16; o; o >>= 1) ss += __shfl_xor_sync(~0u, ss, o);
    if ((tid & 31) == 0) red[tid >> 5] = ss;
    __syncthreads();
    float tot = red[0] + red[1] + red[2] + red[3] + red[4] + red[5];
    float rstd = rsqrtf(tot*(1.f/DM) + 1e-5f);
    rn[tid] = v*rstd*nfw[tid];
    __syncthreads();
    if (tid < 22) {
        float s = hb[tid];
        const float* wr = hw + tid*DM;
        #pragma unroll 4
        for (int k = 0; k < DM; k++) s = fmaf(rn[k], wr[k], s);
        out[b*22 + tid] = s;
    }
}

// ---------------- launcher ----------------
extern "C" void kernel_launch(void* const* d_in, const int* in_sizes, int n_in,
                              void* d_out, int out_size)
{
    const float* x         = (const float*)d_in[0];
    const float* pe_w      = (const float*)d_in[1];
    const float* pe_b      = (const float*)d_in[2];
    const float* cls_token = (const float*)d_in[3];
    const float* pos_embed = (const float*)d_in[4];
    const float* norm_w    = (const float*)d_in[5];
    const float* in_proj_w = (const float*)d_in[6];
    const float* cw        = (const float*)d_in[7];
    const float* cb        = (const float*)d_in[8];
    const float* xproj_w   = (const float*)d_in[9];
    const float* dtproj_w  = (const float*)d_in[10];
    const float* dtproj_b  = (const float*)d_in[11];
    const float* A_log     = (const float*)d_in[12];
    const float* A_b_log   = (const float*)d_in[13];
    const float* Dp        = (const float*)d_in[14];
    const float* outproj_w = (const float*)d_in[15];
    const float* norm_f_w  = (const float*)d_in[16];
    const float* head_w    = (const float*)d_in[17];
    const float* head_b    = (const float*)d_in[18];
    float* out = (float*)d_out;

    k_patch<<<dim3(400, NB), 256>>>(x, pe_w, pe_b, cls_token, pos_embed);

    for (int l = 0; l < DEPTH; l++) {
        k_prenorm<<<(MTOK + 7)/8, 256>>>(norm_w + l*DM);
        k_gemm_tc<0><<<dim3((MTOK + 127)/128, (2*DI)/64), 256>>>(in_proj_w + (size_t)l*2*DI*DM);
        k_conv<<<dim3(LSEQ, NB), DI>>>(cw + l*DI*DCONV, cb + l*DI);
        k_gemm2<<<(2*MTOK + 31)/32, 192>>>(xproj_w + (size_t)l*DXP*DI);
        k_dt<<<2*MTOK/8, DI>>>(dtproj_w + (size_t)l*DI*DTRANK, dtproj_b + l*DI);
        k_scan<<<dim3(DI/16, NB, 2), 256>>>(A_log + (size_t)l*DI*DSTATE,
                                            A_b_log + (size_t)l*DI*DSTATE,
                                            Dp + l*DI);
        k_gemm_tc<1><<<dim3((MTOK + 63)/64, DM/64), 256>>>(outproj_w + (size_t)l*DM*DI);
    }

    k_head<<<NB, DM>>>(norm_f_w, head_w, head_b, out);
}